// round 5
// baseline (speedup 1.0000x reference)
#include <cuda_runtime.h>
#include <cstdint>
#include <float.h>
#include <math.h>

#define DIMD   4096
#define NEXP   256
#define TOPK   8
#define MAXT   16384
#define KCH    32
#define NCHUNK (DIMD / KCH)   // 128

// Device-global scratch (allocation-free per harness rules)
__device__ float g_logits[MAXT * NEXP];                  // 16 MB
__device__ float g_wfrag[2 * NCHUNK * 4 * 16 * 32 * 4];  // 8 MB: W split hi/lo, fragment-permuted
__device__ int   g_risky[MAXT];
__device__ int   g_risky_count;

// ---------------------------------------------------------------------------
__device__ __forceinline__ float f2tf32(float x) {
    uint32_t r; asm("cvt.rna.tf32.f32 %0, %1;" : "=r"(r) : "f"(x));
    return __uint_as_float(r);
}
__device__ __forceinline__ uint32_t smem_u32(const void* p) {
    uint32_t a;
    asm("{ .reg .u64 t; cvta.to.shared.u64 t, %1; cvt.u32.u64 %0, t; }" : "=r"(a) : "l"(p));
    return a;
}
__device__ __forceinline__ void cpasync16(uint32_t dst, const void* src) {
    asm volatile("cp.async.cg.shared.global [%0], [%1], 16;" :: "r"(dst), "l"(src));
}
__device__ __forceinline__ void mma_tf32(float* d, const uint32_t* a, const uint32_t* b) {
    asm volatile(
        "mma.sync.aligned.m16n8k8.row.col.f32.tf32.tf32.f32 "
        "{%0,%1,%2,%3}, {%4,%5,%6,%7}, {%8,%9}, {%0,%1,%2,%3};"
        : "+f"(d[0]), "+f"(d[1]), "+f"(d[2]), "+f"(d[3])
        : "r"(a[0]), "r"(a[1]), "r"(a[2]), "r"(a[3]), "r"(b[0]), "r"(b[1]));
}
__device__ __forceinline__ void mma_tf32_z(float* d, const uint32_t* a, const uint32_t* b) {
    asm volatile(
        "mma.sync.aligned.m16n8k8.row.col.f32.tf32.tf32.f32 "
        "{%0,%1,%2,%3}, {%4,%5,%6,%7}, {%8,%9}, {%10,%11,%12,%13};"
        : "=f"(d[0]), "=f"(d[1]), "=f"(d[2]), "=f"(d[3])
        : "r"(a[0]), "r"(a[1]), "r"(a[2]), "r"(a[3]), "r"(b[0]), "r"(b[1]),
          "f"(0.f), "f"(0.f), "f"(0.f), "f"(0.f));
}

#define SWZ(c4) (((c4) & 3) | (((c4) & 4) << 2))
#define SM_A(s)  ((s) * 32768)
#define SM_B(s)  (65536 + (s) * 32768)
#define SM_TOTAL 131072

#define TAU 1e-4f   // decision-margin threshold for risky-token repair

// ---------------------------------------------------------------------------
// W pre-split into 3xTF32 B-fragment layout (also zeroes risky counter).
// ---------------------------------------------------------------------------
__global__ void split_w_kernel(const float* __restrict__ W) {
    if (blockIdx.x == 0 && threadIdx.x == 0) g_risky_count = 0;
    int F = blockIdx.x * blockDim.x + threadIdx.x;
    int lane = F & 31;
    int nt   = (F >> 5) & 15;
    int kk   = (F >> 9) & 3;
    int c    = (F >> 11) & 127;
    int nblk = F >> 18;
    int n = nblk * 128 + nt * 8 + (lane >> 2);
    int k = c * 32 + kk * 8 + (lane & 3);
    float b0 = W[(size_t)n * DIMD + k];
    float b1 = W[(size_t)n * DIMD + k + 4];
    float h0 = f2tf32(b0), l0 = f2tf32(b0 - h0);
    float h1 = f2tf32(b1), l1 = f2tf32(b1 - h1);
    ((float4*)g_wfrag)[F] = make_float4(h0, l0, h1, l1);
}

// ---------------------------------------------------------------------------
// 3xTF32 GEMM via mma.sync (m16n8k8) — unchanged from R4 (weights validated).
// ---------------------------------------------------------------------------
__global__ void __launch_bounds__(256, 1)
gate_gemm_tf32(const float* __restrict__ X)
{
    extern __shared__ char smem[];
    const uint32_t sb = smem_u32(smem);
    const int tid  = threadIdx.x;
    const int lane = tid & 31;
    const int wid  = tid >> 5;
    const int n0   = blockIdx.x * 128;
    const int nblk = blockIdx.x;
    const int m0   = blockIdx.y * 128;

    const int wm = wid & 1;
    const int wn = wid >> 1;

    float acc[4][4][4];
#pragma unroll
    for (int i = 0; i < 4; i++)
#pragma unroll
        for (int j = 0; j < 4; j++)
#pragma unroll
            for (int r = 0; r < 4; r++) acc[i][j][r] = 0.f;

    float4 xr[4];
    auto ldX = [&](int c) {
#pragma unroll
        for (int u = 0; u < 4; u++) {
            int q = tid + u * 256;
            int m = q >> 3, c4 = q & 7;
            xr[u] = *(const float4*)(X + (size_t)(m0 + m) * DIMD + c * KCH + c4 * 4);
        }
    };
    auto stsA = [&](int s) {
        char* aS = smem + SM_A(s);
#pragma unroll
        for (int u = 0; u < 4; u++) {
            int q = tid + u * 256;
            int m = q >> 3, c4 = q & 7;
            int kk = c4 >> 1, grp = c4 & 1, mt = m >> 4;
            int rm = m & 15;
            int fo = (rm >> 3) * 2;
            int lane0 = (rm & 7) * 4;
            int sw = SWZ(c4);
            char* base = aS + ((((kk * 8 + mt) * 2 + grp) << 9)) + fo * 4;
            float v[4] = {xr[u].x, xr[u].y, xr[u].z, xr[u].w};
#pragma unroll
            for (int e = 0; e < 4; e++) {
                float h = f2tf32(v[e]);
                float l = f2tf32(v[e] - h);
                int slot = (lane0 + e) ^ sw;
                *(float2*)(base + (slot << 4)) = make_float2(h, l);
            }
        }
    };
    auto cpB = [&](int c, int s) {
        const float4* src = (const float4*)g_wfrag + ((size_t)nblk * NCHUNK + c) * 2048;
        uint32_t dst = sb + SM_B(s);
#pragma unroll
        for (int u = 0; u < 8; u++) {
            int q = tid + u * 256;
            cpasync16(dst + q * 16, src + q);
        }
    };
    auto compute = [&](int s) {
        const char* aS = smem + SM_A(s);
        const char* bS = smem + SM_B(s);
#pragma unroll
        for (int kk = 0; kk < 4; kk++) {
            float4 ag[4][2];
#pragma unroll
            for (int i = 0; i < 4; i++) {
                int mt = wm * 4 + i;
#pragma unroll
                for (int g = 0; g < 2; g++) {
                    int c4 = kk * 2 + g;
                    int slot = lane ^ SWZ(c4);
                    ag[i][g] = *(const float4*)(aS + (((kk * 8 + mt) * 2 + g) << 9) + (slot << 4));
                }
            }
            float4 bg[4];
#pragma unroll
            for (int j = 0; j < 4; j++) {
                int nt = wn * 4 + j;
                bg[j] = *(const float4*)(bS + (((kk * 16 + nt) << 9)) + (lane << 4));
            }
#pragma unroll
            for (int i = 0; i < 4; i++) {
                uint32_t ah[4] = {__float_as_uint(ag[i][0].x), __float_as_uint(ag[i][0].z),
                                  __float_as_uint(ag[i][1].x), __float_as_uint(ag[i][1].z)};
                uint32_t al[4] = {__float_as_uint(ag[i][0].y), __float_as_uint(ag[i][0].w),
                                  __float_as_uint(ag[i][1].y), __float_as_uint(ag[i][1].w)};
#pragma unroll
                for (int j = 0; j < 4; j++) {
                    uint32_t bh[2] = {__float_as_uint(bg[j].x), __float_as_uint(bg[j].z)};
                    uint32_t bl[2] = {__float_as_uint(bg[j].y), __float_as_uint(bg[j].w)};
                    float dt[4];
                    mma_tf32_z(dt, ah, bh);
                    mma_tf32(dt, ah, bl);
                    mma_tf32(dt, al, bh);
                    acc[i][j][0] += dt[0];
                    acc[i][j][1] += dt[1];
                    acc[i][j][2] += dt[2];
                    acc[i][j][3] += dt[3];
                }
            }
        }
    };

    ldX(0);
    cpB(0, 0);
    asm volatile("cp.async.commit_group;" ::: "memory");
    stsA(0);
    ldX(1);
    __syncthreads();

    for (int c = 0; c < NCHUNK; c++) {
        const int s = c & 1;
        asm volatile("cp.async.wait_group 0;" ::: "memory");
        __syncthreads();
        if (c + 1 < NCHUNK) {
            cpB(c + 1, s ^ 1);
            asm volatile("cp.async.commit_group;" ::: "memory");
            stsA(s ^ 1);
            if (c + 2 < NCHUNK) ldX(c + 2);
        }
        compute(s);
    }

#pragma unroll
    for (int i = 0; i < 4; i++) {
        int row0 = m0 + wm * 64 + i * 16 + (lane >> 2);
#pragma unroll
        for (int j = 0; j < 4; j++) {
            int col = n0 + wn * 32 + j * 8 + (lane & 3) * 2;
            *(float2*)(g_logits + (size_t)row0 * NEXP + col)       = make_float2(acc[i][j][0], acc[i][j][1]);
            *(float2*)(g_logits + (size_t)(row0 + 8) * NEXP + col) = make_float2(acc[i][j][2], acc[i][j][3]);
        }
    }
}

// ---------------------------------------------------------------------------
// Shared routing core. DETECT: measure decision margins, flag risky tokens.
// v[j] holds logit of expert j*32+lane. Arithmetic identical for both callers.
// ---------------------------------------------------------------------------
template <bool DETECT>
__device__ __forceinline__ void route_core(float v[8], int lane, int token,
                                           float* __restrict__ wout,
                                           float* __restrict__ iout, int two_out)
{
    float m = v[0];
#pragma unroll
    for (int j = 1; j < 8; j++) m = fmaxf(m, v[j]);
#pragma unroll
    for (int o = 16; o; o >>= 1) m = fmaxf(m, __shfl_xor_sync(0xffffffffu, m, o));

    float e[8], s = 0.f;
#pragma unroll
    for (int j = 0; j < 8; j++) { e[j] = expf(v[j] - m); s += e[j]; }
#pragma unroll
    for (int o = 16; o; o >>= 1) s += __shfl_xor_sync(0xffffffffu, s, o);
    const float inv = 1.f / s;

    float gm[8];
#pragma unroll
    for (int j = 0; j < 8; j++) {
        float g = v[j];
#pragma unroll
        for (int o = 16; o; o >>= 1) g = fmaxf(g, __shfl_xor_sync(0xffffffffu, g, o));
        gm[j] = g;
    }

    // top-4 groups; round 4 (5th best) only for the margin
    unsigned keep = 0;
    float gv4 = 0.f, gv5 = 0.f;
#pragma unroll
    for (int r = 0; r < 5; r++) {
        int best = -1; float bv = -FLT_MAX;
#pragma unroll
        for (int g = 0; g < 8; g++) {
            if (keep & (1u << g)) continue;
            if (gm[g] > bv) { bv = gm[g]; best = g; }
        }
        if (r < 4) keep |= 1u << best;
        if (r == 3) gv4 = bv;
        if (r == 4) gv5 = bv;
    }
    bool risky = DETECT && (gv4 - gv5 < TAU);

    float mv[8];
#pragma unroll
    for (int j = 0; j < 8; j++) mv[j] = ((keep >> j) & 1u) ? e[j] : -FLT_MAX;

    float prev = 0.f;
#pragma unroll
    for (int r = 0; r < 9; r++) {      // rounds 0..7 emit; round 8 = margin only
        float bv = -FLT_MAX; int bi = NEXP;
#pragma unroll
        for (int j = 0; j < 8; j++) {
            int idx = j * 32 + lane;
            if (mv[j] > bv || (mv[j] == bv && idx < bi)) { bv = mv[j]; bi = idx; }
        }
#pragma unroll
        for (int o = 16; o; o >>= 1) {
            float ov = __shfl_xor_sync(0xffffffffu, bv, o);
            int   oi = __shfl_xor_sync(0xffffffffu, bi, o);
            if (ov > bv || (ov == bv && oi < bi)) { bv = ov; bi = oi; }
        }
        if (DETECT && r > 0 && (prev - bv < TAU * prev)) risky = true;
        prev = bv;
        if (r < 8) {
            if (lane == r) {
                wout[(size_t)token * TOPK + r] = bv * inv;
                if (two_out) iout[(size_t)token * TOPK + r] = (float)bi;
            }
            int jj = bi >> 5, ll = bi & 31;
#pragma unroll
            for (int j = 0; j < 8; j++)
                if (j == jj && lane == ll) mv[j] = -FLT_MAX;
        }
    }

    if (DETECT && risky && lane == 0) {
        int pos = atomicAdd(&g_risky_count, 1);
        g_risky[pos] = token;
    }
}

// ---------------------------------------------------------------------------
__global__ void gate_route_kernel(float* __restrict__ wout,
                                  float* __restrict__ iout,
                                  int T, int two_out)
{
    const int warp = (blockIdx.x * blockDim.x + threadIdx.x) >> 5;
    const int lane = threadIdx.x & 31;
    if (warp >= T) return;
    const float* l = g_logits + (size_t)warp * NEXP;
    float v[8];
#pragma unroll
    for (int j = 0; j < 8; j++) v[j] = l[j * 32 + lane];
    route_core<true>(v, lane, warp, wout, iout, two_out);
}

// ---------------------------------------------------------------------------
// Repair: recompute risky tokens' logits with R1's exact FFMA chain
// (strictly ascending-k fmaf, RN), then rerun identical routing.
// One CTA per 2 risky tokens; thread e = expert e.
// ---------------------------------------------------------------------------
__global__ void __launch_bounds__(256)
repair_kernel(const float* __restrict__ X, const float* __restrict__ W,
              float* __restrict__ wout, float* __restrict__ iout, int two_out)
{
    __shared__ float slog[2][NEXP];
    const int cnt = g_risky_count;
    const int t0  = blockIdx.x * 2;
    if (t0 >= cnt) return;
    const int ntok = (cnt - t0 >= 2) ? 2 : 1;
    const int e = threadIdx.x;

    const int tokA = g_risky[t0];
    const int tokB = (ntok > 1) ? g_risky[t0 + 1] : tokA;

    const float4* wr = (const float4*)(W + (size_t)e * DIMD);
    const float4* xa = (const float4*)(X + (size_t)tokA * DIMD);
    const float4* xb = (const float4*)(X + (size_t)tokB * DIMD);

    float a0 = 0.f, a1 = 0.f;
    for (int q = 0; q < DIMD / 4; q++) {
        float4 w4 = wr[q];
        float4 x4 = xa[q];
        a0 = fmaf(x4.x, w4.x, a0); a0 = fmaf(x4.y, w4.y, a0);
        a0 = fmaf(x4.z, w4.z, a0); a0 = fmaf(x4.w, w4.w, a0);
        float4 y4 = xb[q];
        a1 = fmaf(y4.x, w4.x, a1); a1 = fmaf(y4.y, w4.y, a1);
        a1 = fmaf(y4.z, w4.z, a1); a1 = fmaf(y4.w, w4.w, a1);
    }
    slog[0][e] = a0;
    slog[1][e] = a1;
    __syncthreads();

    const int wid  = threadIdx.x >> 5;
    const int lane = threadIdx.x & 31;
    if (wid < ntok) {
        int token = wid ? tokB : tokA;
        float v[8];
#pragma unroll
        for (int j = 0; j < 8; j++) v[j] = slog[wid][j * 32 + lane];
        route_core<false>(v, lane, token, wout, iout, two_out);
    }
}

// ---------------------------------------------------------------------------
extern "C" void kernel_launch(void* const* d_in, const int* in_sizes, int n_in,
                              void* d_out, int out_size)
{
    const float* X = (const float*)d_in[0];
    const float* W = (const float*)d_in[1];
    const int T = in_sizes[0] / DIMD;   // 16384

    split_w_kernel<<<2048, 256>>>(W);

    cudaFuncSetAttribute(gate_gemm_tf32, cudaFuncAttributeMaxDynamicSharedMemorySize, SM_TOTAL);
    dim3 ggrid(NEXP / 128, T / 128);
    gate_gemm_tf32<<<ggrid, 256, SM_TOTAL>>>(X);

    float* wout = (float*)d_out;
    int two_out = (out_size >= 2 * T * TOPK) ? 1 : 0;
    float* iout = wout + (size_t)T * TOPK;
    gate_route_kernel<<<(T * 32 + 255) / 256, 256>>>(wout, iout, T, two_out);

    // Repair pass: worst case every token risky -> T/2 CTAs; idle CTAs exit fast.
    repair_kernel<<<T / 2, 256>>>(X, W, wout, iout, two_out);
}

// round 6
// speedup vs baseline: 1.2933x; 1.2933x over previous
#include <cuda_runtime.h>
#include <cuda_fp16.h>
#include <cstdint>
#include <float.h>
#include <math.h>

#define DIMD   4096
#define NEXP   256
#define TOPK   8
#define MAXT   16384
#define KCH    32
#define NCHUNK (DIMD / KCH)   // 128

// Device-global scratch (allocation-free per harness rules)
__device__ float g_logits[MAXT * NEXP];            // 16 MB
__device__ uint4 g_wfrag[2 * NCHUNK * 2 * 16 * 32];// 4 MB: W split hi/lo fp16, B-fragment order
__device__ int   g_risky[MAXT];
__device__ int   g_risky_count;

#define TAU 1e-5f   // decision-margin threshold (noise ~5e-7 -> 20x safety)

// ---------------------------------------------------------------------------
__device__ __forceinline__ uint32_t smem_u32(const void* p) {
    uint32_t a;
    asm("{ .reg .u64 t; cvta.to.shared.u64 t, %1; cvt.u32.u64 %0, t; }" : "=r"(a) : "l"(p));
    return a;
}
__device__ __forceinline__ void cpasync16(uint32_t dst, const void* src) {
    asm volatile("cp.async.cg.shared.global [%0], [%1], 16;" :: "r"(dst), "l"(src));
}
__device__ __forceinline__ uint32_t pack_h2(__half a, __half b) {
    __half2 p = __halves2half2(a, b);
    return *reinterpret_cast<uint32_t*>(&p);
}
// chained mma: d += a*b (internal accumulate)
__device__ __forceinline__ void mma_f16(float* d, const uint32_t* a, const uint32_t* b) {
    asm volatile(
        "mma.sync.aligned.m16n8k16.row.col.f32.f16.f16.f32 "
        "{%0,%1,%2,%3}, {%4,%5,%6,%7}, {%8,%9}, {%0,%1,%2,%3};"
        : "+f"(d[0]), "+f"(d[1]), "+f"(d[2]), "+f"(d[3])
        : "r"(a[0]), "r"(a[1]), "r"(a[2]), "r"(a[3]), "r"(b[0]), "r"(b[1]));
}
// fresh-start mma: d = a*b (kills RZ-accumulation bias chains)
__device__ __forceinline__ void mma_f16_z(float* d, const uint32_t* a, const uint32_t* b) {
    asm volatile(
        "mma.sync.aligned.m16n8k16.row.col.f32.f16.f16.f32 "
        "{%0,%1,%2,%3}, {%4,%5,%6,%7}, {%8,%9}, {%10,%11,%12,%13};"
        : "=f"(d[0]), "=f"(d[1]), "=f"(d[2]), "=f"(d[3])
        : "r"(a[0]), "r"(a[1]), "r"(a[2]), "r"(a[3]), "r"(b[0]), "r"(b[1]),
          "f"(0.f), "f"(0.f), "f"(0.f), "f"(0.f));
}
__device__ __forceinline__ void ldsm4(uint32_t* r, uint32_t addr) {
    asm volatile("ldmatrix.sync.aligned.m8n8.x4.shared.b16 {%0,%1,%2,%3}, [%4];"
        : "=r"(r[0]), "=r"(r[1]), "=r"(r[2]), "=r"(r[3]) : "r"(addr));
}

// SMEM layout (bytes): per stage A-hi 8K, A-lo 8K, B 16K. 2 stages = 64 KB.
#define SM_AHI(s) ((s) * 16384)
#define SM_ALO(s) ((s) * 16384 + 8192)
#define SM_B(s)   (32768 + (s) * 16384)
#define SM_TOTAL  65536

// ---------------------------------------------------------------------------
// W pre-split: fp32 -> (fp16 hi, fp16 lo) of W*4096, in exact mma-B-fragment
// order: g_wfrag[nblk][c][kk][nt][lane] = (hi_b0, hi_b1, lo_b0, lo_b1)
//   n = nblk*128 + nt*8 + lane/4; b0: k = c*32+kk*16+(lane%4)*2 +{0,1}; b1: +8
// ---------------------------------------------------------------------------
__global__ void split_w_kernel(const float* __restrict__ W) {
    if (blockIdx.x == 0 && threadIdx.x == 0) g_risky_count = 0;
    int F = blockIdx.x * blockDim.x + threadIdx.x;   // 0..262143
    int lane = F & 31;
    int nt   = (F >> 5) & 15;
    int kk   = (F >> 9) & 1;
    int c    = (F >> 10) & 127;
    int nblk = F >> 17;
    int n  = nblk * 128 + nt * 8 + (lane >> 2);
    int k0 = c * 32 + kk * 16 + (lane & 3) * 2;
    const float* wr = W + (size_t)n * DIMD;
    float2 w01 = *(const float2*)(wr + k0);
    float2 w89 = *(const float2*)(wr + k0 + 8);
    float f0 = w01.x * 4096.f, f1 = w01.y * 4096.f;
    float f2 = w89.x * 4096.f, f3 = w89.y * 4096.f;
    __half h0 = __float2half_rn(f0), h1 = __float2half_rn(f1);
    __half h2 = __float2half_rn(f2), h3 = __float2half_rn(f3);
    __half l0 = __float2half_rn(f0 - __half2float(h0));
    __half l1 = __float2half_rn(f1 - __half2float(h1));
    __half l2 = __float2half_rn(f2 - __half2float(h2));
    __half l3 = __float2half_rn(f3 - __half2float(h3));
    uint4 o;
    o.x = pack_h2(h0, h1); o.y = pack_h2(h2, h3);
    o.z = pack_h2(l0, l1); o.w = pack_h2(l2, l3);
    g_wfrag[F] = o;
}

// ---------------------------------------------------------------------------
// 3x-fp16 GEMM via mma.m16n8k16: logits[t,e] = X[t,:] . W[e,:]
// CTA 128x128, BK=32, 8 warps (warp tile 64x32), 2-stage pipeline.
// ---------------------------------------------------------------------------
__global__ void __launch_bounds__(256, 1)
gate_gemm_f16(const float* __restrict__ X)
{
    extern __shared__ char smem[];
    const uint32_t sb = smem_u32(smem);
    const int tid  = threadIdx.x;
    const int lane = tid & 31;
    const int wid  = tid >> 5;
    const int nblk = blockIdx.x;          // 0..1
    const int n0   = nblk * 128;
    const int m0   = blockIdx.y * 128;

    const int wm = wid & 1;    // m half (64 rows)
    const int wn = wid >> 1;   // n quarter (32 cols)

    float acc[4][4][4];
#pragma unroll
    for (int i = 0; i < 4; i++)
#pragma unroll
        for (int j = 0; j < 4; j++)
#pragma unroll
            for (int r = 0; r < 4; r++) acc[i][j][r] = 0.f;

    float4 xr[4];
    auto ldX = [&](int c) {
#pragma unroll
        for (int u = 0; u < 4; u++) {
            int q = tid + u * 256;
            int m = q >> 3, c4 = q & 7;
            xr[u] = *(const float4*)(X + (size_t)(m0 + m) * DIMD + c * KCH + c4 * 4);
        }
    };
    // A store: hi/lo fp16, ldmatrix-friendly rows of 32 fp16 (64 B) with XOR swizzle
    auto stsA = [&](int s) {
#pragma unroll
        for (int u = 0; u < 4; u++) {
            int q = tid + u * 256;
            int m = q >> 3, c4 = q & 7;
            float v[4] = {xr[u].x, xr[u].y, xr[u].z, xr[u].w};
            __half h[4], l[4];
#pragma unroll
            for (int e = 0; e < 4; e++) {
                h[e] = __float2half_rn(v[e]);
                l[e] = __float2half_rn(v[e] - __half2float(h[e]));
            }
            uint32_t off = m * 64 + ((((c4 >> 1) ^ ((m >> 1) & 3)) << 4)) + ((c4 & 1) << 3);
            *(uint2*)(smem + SM_AHI(s) + off) = make_uint2(pack_h2(h[0], h[1]), pack_h2(h[2], h[3]));
            *(uint2*)(smem + SM_ALO(s) + off) = make_uint2(pack_h2(l[0], l[1]), pack_h2(l[2], l[3]));
        }
    };
    auto cpB = [&](int c, int s) {
        const uint4* src = g_wfrag + ((size_t)nblk * NCHUNK + c) * 1024;
        uint32_t dst = sb + SM_B(s);
#pragma unroll
        for (int u = 0; u < 4; u++) {
            int q = tid + u * 256;   // 0..1023
            cpasync16(dst + q * 16, src + q);
        }
    };
    auto compute = [&](int s) {
        const int r15  = lane & 15;
        const int koff = lane >> 4;
        const int xorv = (r15 >> 1) & 3;
#pragma unroll
        for (int kk = 0; kk < 2; kk++) {
            uint32_t ah[4][4], al[4][4];
#pragma unroll
            for (int i = 0; i < 4; i++) {
                int row = wm * 64 + i * 16 + r15;
                uint32_t off = row * 64 + ((((kk * 2 + koff) ^ xorv)) << 4);
                ldsm4(ah[i], sb + SM_AHI(s) + off);
                ldsm4(al[i], sb + SM_ALO(s) + off);
            }
            uint4 bf[4];
#pragma unroll
            for (int j = 0; j < 4; j++) {
                int nt = wn * 4 + j;
                bf[j] = *(const uint4*)(smem + SM_B(s) + ((kk * 16 + nt) * 32 + lane) * 16);
            }
#pragma unroll
            for (int i = 0; i < 4; i++) {
#pragma unroll
                for (int j = 0; j < 4; j++) {
                    uint32_t bh[2] = {bf[j].x, bf[j].y};
                    uint32_t bl[2] = {bf[j].z, bf[j].w};
                    float dt[4];
                    mma_f16_z(dt, ah[i], bh);
                    mma_f16(dt, ah[i], bl);
                    mma_f16(dt, al[i], bh);
                    acc[i][j][0] += dt[0];
                    acc[i][j][1] += dt[1];
                    acc[i][j][2] += dt[2];
                    acc[i][j][3] += dt[3];
                }
            }
        }
    };

    // prologue
    ldX(0);
    cpB(0, 0);
    asm volatile("cp.async.commit_group;" ::: "memory");
    stsA(0);
    ldX(1);
    __syncthreads();

    for (int c = 0; c < NCHUNK; c++) {
        const int s = c & 1;
        asm volatile("cp.async.wait_group 0;" ::: "memory");
        __syncthreads();
        if (c + 1 < NCHUNK) {
            cpB(c + 1, s ^ 1);
            asm volatile("cp.async.commit_group;" ::: "memory");
            stsA(s ^ 1);
            if (c + 2 < NCHUNK) ldX(c + 2);
        }
        compute(s);
    }

    // epilogue (undo the 4096 W scale)
    const float SCL = 1.f / 4096.f;
#pragma unroll
    for (int i = 0; i < 4; i++) {
        int row0 = m0 + wm * 64 + i * 16 + (lane >> 2);
#pragma unroll
        for (int j = 0; j < 4; j++) {
            int col = n0 + wn * 32 + j * 8 + (lane & 3) * 2;
            *(float2*)(g_logits + (size_t)row0 * NEXP + col) =
                make_float2(acc[i][j][0] * SCL, acc[i][j][1] * SCL);
            *(float2*)(g_logits + (size_t)(row0 + 8) * NEXP + col) =
                make_float2(acc[i][j][2] * SCL, acc[i][j][3] * SCL);
        }
    }
}

// ---------------------------------------------------------------------------
// Shared routing core. DETECT: measure decision margins, flag risky tokens.
// ---------------------------------------------------------------------------
template <bool DETECT>
__device__ __forceinline__ void route_core(float v[8], int lane, int token,
                                           float* __restrict__ wout,
                                           float* __restrict__ iout, int two_out)
{
    float m = v[0];
#pragma unroll
    for (int j = 1; j < 8; j++) m = fmaxf(m, v[j]);
#pragma unroll
    for (int o = 16; o; o >>= 1) m = fmaxf(m, __shfl_xor_sync(0xffffffffu, m, o));

    float e[8], s = 0.f;
#pragma unroll
    for (int j = 0; j < 8; j++) { e[j] = expf(v[j] - m); s += e[j]; }
#pragma unroll
    for (int o = 16; o; o >>= 1) s += __shfl_xor_sync(0xffffffffu, s, o);
    const float inv = 1.f / s;

    float gm[8];
#pragma unroll
    for (int j = 0; j < 8; j++) {
        float g = v[j];
#pragma unroll
        for (int o = 16; o; o >>= 1) g = fmaxf(g, __shfl_xor_sync(0xffffffffu, g, o));
        gm[j] = g;
    }

    unsigned keep = 0;
    float gv4 = 0.f, gv5 = 0.f;
#pragma unroll
    for (int r = 0; r < 5; r++) {
        int best = -1; float bv = -FLT_MAX;
#pragma unroll
        for (int g = 0; g < 8; g++) {
            if (keep & (1u << g)) continue;
            if (gm[g] > bv) { bv = gm[g]; best = g; }
        }
        if (r < 4) keep |= 1u << best;
        if (r == 3) gv4 = bv;
        if (r == 4) gv5 = bv;
    }
    bool risky = DETECT && (gv4 - gv5 < TAU);   // logit-scale margin

    float mv[8];
#pragma unroll
    for (int j = 0; j < 8; j++) mv[j] = ((keep >> j) & 1u) ? e[j] : -FLT_MAX;

    float prev = 0.f;
#pragma unroll
    for (int r = 0; r < 9; r++) {
        float bv = -FLT_MAX; int bi = NEXP;
#pragma unroll
        for (int j = 0; j < 8; j++) {
            int idx = j * 32 + lane;
            if (mv[j] > bv || (mv[j] == bv && idx < bi)) { bv = mv[j]; bi = idx; }
        }
#pragma unroll
        for (int o = 16; o; o >>= 1) {
            float ov = __shfl_xor_sync(0xffffffffu, bv, o);
            int   oi = __shfl_xor_sync(0xffffffffu, bi, o);
            if (ov > bv || (ov == bv && oi < bi)) { bv = ov; bi = oi; }
        }
        if (DETECT && r > 0 && (prev - bv < TAU * prev)) risky = true;
        prev = bv;
        if (r < 8) {
            if (lane == r) {
                wout[(size_t)token * TOPK + r] = bv * inv;
                if (two_out) iout[(size_t)token * TOPK + r] = (float)bi;
            }
            int jj = bi >> 5, ll = bi & 31;
#pragma unroll
            for (int j = 0; j < 8; j++)
                if (j == jj && lane == ll) mv[j] = -FLT_MAX;
        }
    }

    if (DETECT && risky && lane == 0) {
        int pos = atomicAdd(&g_risky_count, 1);
        g_risky[pos] = token;
    }
}

// ---------------------------------------------------------------------------
__global__ void gate_route_kernel(float* __restrict__ wout,
                                  float* __restrict__ iout,
                                  int T, int two_out)
{
    const int warp = (blockIdx.x * blockDim.x + threadIdx.x) >> 5;
    const int lane = threadIdx.x & 31;
    if (warp >= T) return;
    const float* l = g_logits + (size_t)warp * NEXP;
    float v[8];
#pragma unroll
    for (int j = 0; j < 8; j++) v[j] = l[j * 32 + lane];
    route_core<true>(v, lane, warp, wout, iout, two_out);
}

// ---------------------------------------------------------------------------
// Repair: recompute risky tokens' logits with R1's exact FFMA chain
// (strictly ascending-k fmaf, RN), rerun routing. 8 tokens per CTA so the
// 4 MB W read is amortized 8x. Thread e = expert e.
// ---------------------------------------------------------------------------
__global__ void __launch_bounds__(256)
repair_kernel(const float* __restrict__ X, const float* __restrict__ W,
              float* __restrict__ wout, float* __restrict__ iout, int two_out)
{
    __shared__ float slog[8][NEXP];
    const int cnt = g_risky_count;
    const int t0  = blockIdx.x * 8;
    if (t0 >= cnt) return;
    const int e = threadIdx.x;

    int toks[8];
#pragma unroll
    for (int tt = 0; tt < 8; tt++) {
        int idx = t0 + tt;
        toks[tt] = g_risky[idx < cnt ? idx : cnt - 1];
    }

    const float4* wr = (const float4*)(W + (size_t)e * DIMD);
    const float4* xp[8];
#pragma unroll
    for (int tt = 0; tt < 8; tt++) xp[tt] = (const float4*)(X + (size_t)toks[tt] * DIMD);

    float a[8];
#pragma unroll
    for (int tt = 0; tt < 8; tt++) a[tt] = 0.f;

    for (int q = 0; q < DIMD / 4; q++) {
        float4 w4 = wr[q];
#pragma unroll
        for (int tt = 0; tt < 8; tt++) {
            float4 x4 = xp[tt][q];
            a[tt] = fmaf(x4.x, w4.x, a[tt]);
            a[tt] = fmaf(x4.y, w4.y, a[tt]);
            a[tt] = fmaf(x4.z, w4.z, a[tt]);
            a[tt] = fmaf(x4.w, w4.w, a[tt]);
        }
    }
#pragma unroll
    for (int tt = 0; tt < 8; tt++) slog[tt][e] = a[tt];
    __syncthreads();

    const int wid  = threadIdx.x >> 5;
    const int lane = threadIdx.x & 31;
    // duplicate-token warps write identical values: benign
    int token = toks[wid];
    float v[8];
#pragma unroll
    for (int j = 0; j < 8; j++) v[j] = slog[wid][j * 32 + lane];
    route_core<false>(v, lane, token, wout, iout, two_out);
}

// ---------------------------------------------------------------------------
extern "C" void kernel_launch(void* const* d_in, const int* in_sizes, int n_in,
                              void* d_out, int out_size)
{
    const float* X = (const float*)d_in[0];
    const float* W = (const float*)d_in[1];
    const int T = in_sizes[0] / DIMD;   // 16384

    split_w_kernel<<<1024, 256>>>(W);

    cudaFuncSetAttribute(gate_gemm_f16, cudaFuncAttributeMaxDynamicSharedMemorySize, SM_TOTAL);
    dim3 ggrid(NEXP / 128, T / 128);   // (2, 128): nblk-major -> X shared in L2
    gate_gemm_f16<<<ggrid, 256, SM_TOTAL>>>(X);

    float* wout = (float*)d_out;
    int two_out = (out_size >= 2 * T * TOPK) ? 1 : 0;
    float* iout = wout + (size_t)T * TOPK;
    gate_route_kernel<<<(T * 32 + 255) / 256, 256>>>(wout, iout, T, two_out);

    repair_kernel<<<(T + 7) / 8, 256>>>(X, W, wout, iout, two_out);
}

// round 7
// speedup vs baseline: 2.0776x; 1.6064x over previous
#include <cuda_runtime.h>
#include <cuda_fp16.h>
#include <cstdint>
#include <float.h>
#include <math.h>

#define DIMD   4096
#define NEXP   256
#define TOPK   8
#define MAXT   16384
#define KCH    32
#define NCHUNK (DIMD / KCH)   // 128

// Device-global scratch (allocation-free per harness rules)
__device__ float g_logits[MAXT * NEXP];            // 16 MB
__device__ uint4 g_wfrag[2 * NCHUNK * 2 * 16 * 32];// 4 MB: W split hi/lo fp16, B-fragment order
__device__ int   g_risky[MAXT];
__device__ int   g_risky_count;

#define TAU 1e-5f   // decision-margin threshold (noise ~5e-7 -> 20x safety)

// ---------------------------------------------------------------------------
__device__ __forceinline__ uint32_t smem_u32(const void* p) {
    uint32_t a;
    asm("{ .reg .u64 t; cvta.to.shared.u64 t, %1; cvt.u32.u64 %0, t; }" : "=r"(a) : "l"(p));
    return a;
}
__device__ __forceinline__ void cpasync16(uint32_t dst, const void* src) {
    asm volatile("cp.async.cg.shared.global [%0], [%1], 16;" :: "r"(dst), "l"(src));
}
__device__ __forceinline__ uint32_t pack_h2(__half a, __half b) {
    __half2 p = __halves2half2(a, b);
    return *reinterpret_cast<uint32_t*>(&p);
}
__device__ __forceinline__ void mma_f16(float* d, const uint32_t* a, const uint32_t* b) {
    asm volatile(
        "mma.sync.aligned.m16n8k16.row.col.f32.f16.f16.f32 "
        "{%0,%1,%2,%3}, {%4,%5,%6,%7}, {%8,%9}, {%0,%1,%2,%3};"
        : "+f"(d[0]), "+f"(d[1]), "+f"(d[2]), "+f"(d[3])
        : "r"(a[0]), "r"(a[1]), "r"(a[2]), "r"(a[3]), "r"(b[0]), "r"(b[1]));
}
__device__ __forceinline__ void mma_f16_z(float* d, const uint32_t* a, const uint32_t* b) {
    asm volatile(
        "mma.sync.aligned.m16n8k16.row.col.f32.f16.f16.f32 "
        "{%0,%1,%2,%3}, {%4,%5,%6,%7}, {%8,%9}, {%10,%11,%12,%13};"
        : "=f"(d[0]), "=f"(d[1]), "=f"(d[2]), "=f"(d[3])
        : "r"(a[0]), "r"(a[1]), "r"(a[2]), "r"(a[3]), "r"(b[0]), "r"(b[1]),
          "f"(0.f), "f"(0.f), "f"(0.f), "f"(0.f));
}
__device__ __forceinline__ void ldsm4(uint32_t* r, uint32_t addr) {
    asm volatile("ldmatrix.sync.aligned.m8n8.x4.shared.b16 {%0,%1,%2,%3}, [%4];"
        : "=r"(r[0]), "=r"(r[1]), "=r"(r[2]), "=r"(r[3]) : "r"(addr));
}

// SMEM layout (bytes): per stage A-hi 8K, A-lo 8K, B 16K. 2 stages = 64 KB.
#define SM_AHI(s) ((s) * 16384)
#define SM_ALO(s) ((s) * 16384 + 8192)
#define SM_B(s)   (32768 + (s) * 16384)
#define SM_TOTAL  65536

// ---------------------------------------------------------------------------
// W pre-split: fp32 -> (fp16 hi, fp16 lo) of W*4096, mma-B-fragment order.
// ---------------------------------------------------------------------------
__global__ void split_w_kernel(const float* __restrict__ W) {
    if (blockIdx.x == 0 && threadIdx.x == 0) g_risky_count = 0;
    int F = blockIdx.x * blockDim.x + threadIdx.x;   // 0..262143
    int lane = F & 31;
    int nt   = (F >> 5) & 15;
    int kk   = (F >> 9) & 1;
    int c    = (F >> 10) & 127;
    int nblk = F >> 17;
    int n  = nblk * 128 + nt * 8 + (lane >> 2);
    int k0 = c * 32 + kk * 16 + (lane & 3) * 2;
    const float* wr = W + (size_t)n * DIMD;
    float2 w01 = *(const float2*)(wr + k0);
    float2 w89 = *(const float2*)(wr + k0 + 8);
    float f0 = w01.x * 4096.f, f1 = w01.y * 4096.f;
    float f2 = w89.x * 4096.f, f3 = w89.y * 4096.f;
    __half h0 = __float2half_rn(f0), h1 = __float2half_rn(f1);
    __half h2 = __float2half_rn(f2), h3 = __float2half_rn(f3);
    __half l0 = __float2half_rn(f0 - __half2float(h0));
    __half l1 = __float2half_rn(f1 - __half2float(h1));
    __half l2 = __float2half_rn(f2 - __half2float(h2));
    __half l3 = __float2half_rn(f3 - __half2float(h3));
    uint4 o;
    o.x = pack_h2(h0, h1); o.y = pack_h2(h2, h3);
    o.z = pack_h2(l0, l1); o.w = pack_h2(l2, l3);
    g_wfrag[F] = o;
}

// ---------------------------------------------------------------------------
// 3x-fp16 GEMM via mma.m16n8k16 (unchanged from R6 — validated 8.4e-7).
// ---------------------------------------------------------------------------
__global__ void __launch_bounds__(256, 1)
gate_gemm_f16(const float* __restrict__ X)
{
    extern __shared__ char smem[];
    const uint32_t sb = smem_u32(smem);
    const int tid  = threadIdx.x;
    const int lane = tid & 31;
    const int wid  = tid >> 5;
    const int nblk = blockIdx.x;
    const int n0   = nblk * 128;
    const int m0   = blockIdx.y * 128;

    const int wm = wid & 1;
    const int wn = wid >> 1;

    float acc[4][4][4];
#pragma unroll
    for (int i = 0; i < 4; i++)
#pragma unroll
        for (int j = 0; j < 4; j++)
#pragma unroll
            for (int r = 0; r < 4; r++) acc[i][j][r] = 0.f;

    float4 xr[4];
    auto ldX = [&](int c) {
#pragma unroll
        for (int u = 0; u < 4; u++) {
            int q = tid + u * 256;
            int m = q >> 3, c4 = q & 7;
            xr[u] = *(const float4*)(X + (size_t)(m0 + m) * DIMD + c * KCH + c4 * 4);
        }
    };
    auto stsA = [&](int s) {
#pragma unroll
        for (int u = 0; u < 4; u++) {
            int q = tid + u * 256;
            int m = q >> 3, c4 = q & 7;
            float v[4] = {xr[u].x, xr[u].y, xr[u].z, xr[u].w};
            __half h[4], l[4];
#pragma unroll
            for (int e = 0; e < 4; e++) {
                h[e] = __float2half_rn(v[e]);
                l[e] = __float2half_rn(v[e] - __half2float(h[e]));
            }
            uint32_t off = m * 64 + ((((c4 >> 1) ^ ((m >> 1) & 3)) << 4)) + ((c4 & 1) << 3);
            *(uint2*)(smem + SM_AHI(s) + off) = make_uint2(pack_h2(h[0], h[1]), pack_h2(h[2], h[3]));
            *(uint2*)(smem + SM_ALO(s) + off) = make_uint2(pack_h2(l[0], l[1]), pack_h2(l[2], l[3]));
        }
    };
    auto cpB = [&](int c, int s) {
        const uint4* src = g_wfrag + ((size_t)nblk * NCHUNK + c) * 1024;
        uint32_t dst = sb + SM_B(s);
#pragma unroll
        for (int u = 0; u < 4; u++) {
            int q = tid + u * 256;
            cpasync16(dst + q * 16, src + q);
        }
    };
    auto compute = [&](int s) {
        const int r15  = lane & 15;
        const int koff = lane >> 4;
        const int xorv = (r15 >> 1) & 3;
#pragma unroll
        for (int kk = 0; kk < 2; kk++) {
            uint32_t ah[4][4], al[4][4];
#pragma unroll
            for (int i = 0; i < 4; i++) {
                int row = wm * 64 + i * 16 + r15;
                uint32_t off = row * 64 + ((((kk * 2 + koff) ^ xorv)) << 4);
                ldsm4(ah[i], sb + SM_AHI(s) + off);
                ldsm4(al[i], sb + SM_ALO(s) + off);
            }
            uint4 bf[4];
#pragma unroll
            for (int j = 0; j < 4; j++) {
                int nt = wn * 4 + j;
                bf[j] = *(const uint4*)(smem + SM_B(s) + ((kk * 16 + nt) * 32 + lane) * 16);
            }
#pragma unroll
            for (int i = 0; i < 4; i++) {
#pragma unroll
                for (int j = 0; j < 4; j++) {
                    uint32_t bh[2] = {bf[j].x, bf[j].y};
                    uint32_t bl[2] = {bf[j].z, bf[j].w};
                    float dt[4];
                    mma_f16_z(dt, ah[i], bh);
                    mma_f16(dt, ah[i], bl);
                    mma_f16(dt, al[i], bh);
                    acc[i][j][0] += dt[0];
                    acc[i][j][1] += dt[1];
                    acc[i][j][2] += dt[2];
                    acc[i][j][3] += dt[3];
                }
            }
        }
    };

    ldX(0);
    cpB(0, 0);
    asm volatile("cp.async.commit_group;" ::: "memory");
    stsA(0);
    ldX(1);
    __syncthreads();

    for (int c = 0; c < NCHUNK; c++) {
        const int s = c & 1;
        asm volatile("cp.async.wait_group 0;" ::: "memory");
        __syncthreads();
        if (c + 1 < NCHUNK) {
            cpB(c + 1, s ^ 1);
            asm volatile("cp.async.commit_group;" ::: "memory");
            stsA(s ^ 1);
            if (c + 2 < NCHUNK) ldX(c + 2);
        }
        compute(s);
    }

    const float SCL = 1.f / 4096.f;
#pragma unroll
    for (int i = 0; i < 4; i++) {
        int row0 = m0 + wm * 64 + i * 16 + (lane >> 2);
#pragma unroll
        for (int j = 0; j < 4; j++) {
            int col = n0 + wn * 32 + j * 8 + (lane & 3) * 2;
            *(float2*)(g_logits + (size_t)row0 * NEXP + col) =
                make_float2(acc[i][j][0] * SCL, acc[i][j][1] * SCL);
            *(float2*)(g_logits + (size_t)(row0 + 8) * NEXP + col) =
                make_float2(acc[i][j][2] * SCL, acc[i][j][3] * SCL);
        }
    }
}

// ---------------------------------------------------------------------------
// Shared routing core. DETECT: measure decision margins, flag risky tokens.
// ---------------------------------------------------------------------------
template <bool DETECT>
__device__ __forceinline__ void route_core(float v[8], int lane, int token,
                                           float* __restrict__ wout,
                                           float* __restrict__ iout, int two_out)
{
    float m = v[0];
#pragma unroll
    for (int j = 1; j < 8; j++) m = fmaxf(m, v[j]);
#pragma unroll
    for (int o = 16; o; o >>= 1) m = fmaxf(m, __shfl_xor_sync(0xffffffffu, m, o));

    float e[8], s = 0.f;
#pragma unroll
    for (int j = 0; j < 8; j++) { e[j] = expf(v[j] - m); s += e[j]; }
#pragma unroll
    for (int o = 16; o; o >>= 1) s += __shfl_xor_sync(0xffffffffu, s, o);
    const float inv = 1.f / s;

    float gm[8];
#pragma unroll
    for (int j = 0; j < 8; j++) {
        float g = v[j];
#pragma unroll
        for (int o = 16; o; o >>= 1) g = fmaxf(g, __shfl_xor_sync(0xffffffffu, g, o));
        gm[j] = g;
    }

    unsigned keep = 0;
    float gv4 = 0.f, gv5 = 0.f;
#pragma unroll
    for (int r = 0; r < 5; r++) {
        int best = -1; float bv = -FLT_MAX;
#pragma unroll
        for (int g = 0; g < 8; g++) {
            if (keep & (1u << g)) continue;
            if (gm[g] > bv) { bv = gm[g]; best = g; }
        }
        if (r < 4) keep |= 1u << best;
        if (r == 3) gv4 = bv;
        if (r == 4) gv5 = bv;
    }
    bool risky = DETECT && (gv4 - gv5 < TAU);

    float mv[8];
#pragma unroll
    for (int j = 0; j < 8; j++) mv[j] = ((keep >> j) & 1u) ? e[j] : -FLT_MAX;

    float prev = 0.f;
#pragma unroll
    for (int r = 0; r < 9; r++) {
        float bv = -FLT_MAX; int bi = NEXP;
#pragma unroll
        for (int j = 0; j < 8; j++) {
            int idx = j * 32 + lane;
            if (mv[j] > bv || (mv[j] == bv && idx < bi)) { bv = mv[j]; bi = idx; }
        }
#pragma unroll
        for (int o = 16; o; o >>= 1) {
            float ov = __shfl_xor_sync(0xffffffffu, bv, o);
            int   oi = __shfl_xor_sync(0xffffffffu, bi, o);
            if (ov > bv || (ov == bv && oi < bi)) { bv = ov; bi = oi; }
        }
        if (DETECT && r > 0 && (prev - bv < TAU * prev)) risky = true;
        prev = bv;
        if (r < 8) {
            if (lane == r) {
                wout[(size_t)token * TOPK + r] = bv * inv;
                if (two_out) iout[(size_t)token * TOPK + r] = (float)bi;
            }
            int jj = bi >> 5, ll = bi & 31;
#pragma unroll
            for (int j = 0; j < 8; j++)
                if (j == jj && lane == ll) mv[j] = -FLT_MAX;
        }
    }

    if (DETECT && risky && lane == 0) {
        int pos = atomicAdd(&g_risky_count, 1);
        g_risky[pos] = token;
    }
}

// ---------------------------------------------------------------------------
__global__ void gate_route_kernel(float* __restrict__ wout,
                                  float* __restrict__ iout,
                                  int T, int two_out)
{
    const int warp = (blockIdx.x * blockDim.x + threadIdx.x) >> 5;
    const int lane = threadIdx.x & 31;
    if (warp >= T) return;
    const float* l = g_logits + (size_t)warp * NEXP;
    float v[8];
#pragma unroll
    for (int j = 0; j < 8; j++) v[j] = l[j * 32 + lane];
    route_core<true>(v, lane, warp, wout, iout, two_out);
}

// ---------------------------------------------------------------------------
// Repair v2: one CTA per risky token. Stage X row + W k-chunks in smem with
// coalesced gmem loads; thread e runs R1's EXACT ascending-k fmaf chain.
// Row stride 65 floats -> conflict-free LDS across a warp.
// ---------------------------------------------------------------------------
#define RCH      64
#define RSTRIDE  65
#define RSM_SIZE ((DIMD + NEXP * RSTRIDE) * 4)   // 16384 + 66560 bytes

__global__ void __launch_bounds__(256)
repair_kernel(const float* __restrict__ X, const float* __restrict__ W,
              float* __restrict__ wout, float* __restrict__ iout, int two_out)
{
    extern __shared__ float rsm[];   // sx[4096] | sw[256 * 65]
    float* sx = rsm;
    float* sw = rsm + DIMD;
    __shared__ float slog[NEXP];

    const int cnt = g_risky_count;
    const int e   = threadIdx.x;

    for (int ti = blockIdx.x; ti < cnt; ti += gridDim.x) {
        const int token = g_risky[ti];

        // stage X row (coalesced float4)
        const float4* xsrc = (const float4*)(X + (size_t)token * DIMD);
#pragma unroll
        for (int u = 0; u < 4; u++)
            ((float4*)sx)[e + u * 256] = xsrc[e + u * 256];

        float a = 0.f;
        for (int ck = 0; ck < DIMD / RCH; ck++) {
            __syncthreads();   // sw reusable; sx ready (first iter)
            // stage W chunk [256][RCH]: 4096 float4, coalesced along k
#pragma unroll
            for (int u = 0; u < 16; u++) {
                int idx = e + u * 256;
                int row = idx >> 4, c4 = idx & 15;
                float4 w4 = *(const float4*)(W + (size_t)row * DIMD + ck * RCH + c4 * 4);
                float* d = sw + row * RSTRIDE + c4 * 4;
                d[0] = w4.x; d[1] = w4.y; d[2] = w4.z; d[3] = w4.w;
            }
            __syncthreads();
            const float* wr = sw + e * RSTRIDE;
            const float* xc = sx + ck * RCH;
#pragma unroll
            for (int k = 0; k < RCH; k++)
                a = fmaf(xc[k], wr[k], a);   // strictly ascending k == R1 chain
        }

        slog[e] = a;
        __syncthreads();
        if (e < 32) {
            float v[8];
#pragma unroll
            for (int j = 0; j < 8; j++) v[j] = slog[j * 32 + e];
            route_core<false>(v, e, token, wout, iout, two_out);
        }
        __syncthreads();   // protect slog/sx before next token
    }
}

// ---------------------------------------------------------------------------
extern "C" void kernel_launch(void* const* d_in, const int* in_sizes, int n_in,
                              void* d_out, int out_size)
{
    const float* X = (const float*)d_in[0];
    const float* W = (const float*)d_in[1];
    const int T = in_sizes[0] / DIMD;   // 16384

    split_w_kernel<<<1024, 256>>>(W);

    cudaFuncSetAttribute(gate_gemm_f16, cudaFuncAttributeMaxDynamicSharedMemorySize, SM_TOTAL);
    dim3 ggrid(NEXP / 128, T / 128);
    gate_gemm_f16<<<ggrid, 256, SM_TOTAL>>>(X);

    float* wout = (float*)d_out;
    int two_out = (out_size >= 2 * T * TOPK) ? 1 : 0;
    float* iout = wout + (size_t)T * TOPK;
    gate_route_kernel<<<(T * 32 + 255) / 256, 256>>>(wout, iout, T, two_out);

    cudaFuncSetAttribute(repair_kernel, cudaFuncAttributeMaxDynamicSharedMemorySize, RSM_SIZE);
    repair_kernel<<<256, 256, RSM_SIZE>>>(X, W, wout, iout, two_out);
}

// round 8
// speedup vs baseline: 2.1545x; 1.0370x over previous
#include <cuda_runtime.h>
#include <cuda_fp16.h>
#include <cstdint>
#include <float.h>
#include <math.h>

#define DIMD   4096
#define NEXP   256
#define TOPK   8
#define MAXT   16384
#define KCH    32
#define NCHUNK (DIMD / KCH)   // 128

// Device-global scratch (allocation-free per harness rules)
__device__ float g_logits[MAXT * NEXP];            // 16 MB
__device__ uint4 g_wfrag[2 * NCHUNK * 2 * 16 * 32];// 4 MB: W split hi/lo fp16, B-fragment order
__device__ float4 g_wq[NEXP * (DIMD / 4)];         // 4 MB: W transposed k-major (repair path)
__device__ int   g_risky[MAXT];
__device__ int   g_risky_count;

#define TAU 1e-5f   // decision-margin threshold (noise ~5e-7 -> 20x safety)

// ---------------------------------------------------------------------------
__device__ __forceinline__ uint32_t smem_u32(const void* p) {
    uint32_t a;
    asm("{ .reg .u64 t; cvta.to.shared.u64 t, %1; cvt.u32.u64 %0, t; }" : "=r"(a) : "l"(p));
    return a;
}
__device__ __forceinline__ void cpasync16(uint32_t dst, const void* src) {
    asm volatile("cp.async.cg.shared.global [%0], [%1], 16;" :: "r"(dst), "l"(src));
}
__device__ __forceinline__ uint32_t pack_h2(__half a, __half b) {
    __half2 p = __halves2half2(a, b);
    return *reinterpret_cast<uint32_t*>(&p);
}
__device__ __forceinline__ void mma_f16(float* d, const uint32_t* a, const uint32_t* b) {
    asm volatile(
        "mma.sync.aligned.m16n8k16.row.col.f32.f16.f16.f32 "
        "{%0,%1,%2,%3}, {%4,%5,%6,%7}, {%8,%9}, {%0,%1,%2,%3};"
        : "+f"(d[0]), "+f"(d[1]), "+f"(d[2]), "+f"(d[3])
        : "r"(a[0]), "r"(a[1]), "r"(a[2]), "r"(a[3]), "r"(b[0]), "r"(b[1]));
}
__device__ __forceinline__ void mma_f16_z(float* d, const uint32_t* a, const uint32_t* b) {
    asm volatile(
        "mma.sync.aligned.m16n8k16.row.col.f32.f16.f16.f32 "
        "{%0,%1,%2,%3}, {%4,%5,%6,%7}, {%8,%9}, {%10,%11,%12,%13};"
        : "=f"(d[0]), "=f"(d[1]), "=f"(d[2]), "=f"(d[3])
        : "r"(a[0]), "r"(a[1]), "r"(a[2]), "r"(a[3]), "r"(b[0]), "r"(b[1]),
          "f"(0.f), "f"(0.f), "f"(0.f), "f"(0.f));
}
__device__ __forceinline__ void ldsm4(uint32_t* r, uint32_t addr) {
    asm volatile("ldmatrix.sync.aligned.m8n8.x4.shared.b16 {%0,%1,%2,%3}, [%4];"
        : "=r"(r[0]), "=r"(r[1]), "=r"(r[2]), "=r"(r[3]) : "r"(addr));
}

// SMEM: per stage A-hi 8K | A-lo 8K | B 8K = 24K; 2 stages = 48 KB (occ 2 fits)
#define SM_AHI(s) ((s) * 24576)
#define SM_ALO(s) ((s) * 24576 + 8192)
#define SM_B(s)   ((s) * 24576 + 16384)
#define SM_TOTAL  49152

// ---------------------------------------------------------------------------
// W pre-split: fp32 -> (fp16 hi, fp16 lo) of W*4096, mma-B-fragment order.
// ---------------------------------------------------------------------------
__global__ void split_w_kernel(const float* __restrict__ W) {
    if (blockIdx.x == 0 && threadIdx.x == 0) g_risky_count = 0;
    int F = blockIdx.x * blockDim.x + threadIdx.x;   // 0..262143
    int lane = F & 31;
    int nt   = (F >> 5) & 15;
    int kk   = (F >> 9) & 1;
    int c    = (F >> 10) & 127;
    int nblk = F >> 17;
    int n  = nblk * 128 + nt * 8 + (lane >> 2);
    int k0 = c * 32 + kk * 16 + (lane & 3) * 2;
    const float* wr = W + (size_t)n * DIMD;
    float2 w01 = *(const float2*)(wr + k0);
    float2 w89 = *(const float2*)(wr + k0 + 8);
    float f0 = w01.x * 4096.f, f1 = w01.y * 4096.f;
    float f2 = w89.x * 4096.f, f3 = w89.y * 4096.f;
    __half h0 = __float2half_rn(f0), h1 = __float2half_rn(f1);
    __half h2 = __float2half_rn(f2), h3 = __float2half_rn(f3);
    __half l0 = __float2half_rn(f0 - __half2float(h0));
    __half l1 = __float2half_rn(f1 - __half2float(h1));
    __half l2 = __float2half_rn(f2 - __half2float(h2));
    __half l3 = __float2half_rn(f3 - __half2float(h3));
    uint4 o;
    o.x = pack_h2(h0, h1); o.y = pack_h2(h2, h3);
    o.z = pack_h2(l0, l1); o.w = pack_h2(l2, l3);
    g_wfrag[F] = o;
}

// ---------------------------------------------------------------------------
// W transpose for repair: g_wq[k4 * 256 + e] = W[e][4*k4 .. 4*k4+3]
// ---------------------------------------------------------------------------
__global__ void transpose_w_kernel(const float* __restrict__ W) {
    int i = blockIdx.x * blockDim.x + threadIdx.x;   // 0..262143
    int e  = i & 255;
    int k4 = i >> 8;
    g_wq[i] = *(const float4*)(W + (size_t)e * DIMD + k4 * 4);
}

// ---------------------------------------------------------------------------
// 3x-fp16 GEMM via mma.m16n8k16. CTA tile 128x64, BK=32, 8 warps
// (warp tile 32x32), 2-stage pipeline, occupancy 2.
// ---------------------------------------------------------------------------
__global__ void __launch_bounds__(256, 2)
gate_gemm_f16(const float* __restrict__ X)
{
    extern __shared__ char smem[];
    const uint32_t sb = smem_u32(smem);
    const int tid  = threadIdx.x;
    const int lane = tid & 31;
    const int wid  = tid >> 5;
    const int bx   = blockIdx.x;          // 0..3 (64-expert blocks)
    const int nblk = bx >> 1;             // g_wfrag major block (128 experts)
    const int nhalf= bx & 1;              // which 8-nt half
    const int n0   = bx * 64;
    const int m0   = blockIdx.y * 128;

    const int wm = wid & 3;    // m quarter (32 rows)
    const int wn = wid >> 2;   // n half (32 cols)

    float acc[2][4][4];
#pragma unroll
    for (int i = 0; i < 2; i++)
#pragma unroll
        for (int j = 0; j < 4; j++)
#pragma unroll
            for (int r = 0; r < 4; r++) acc[i][j][r] = 0.f;

    float4 xr[4];
    auto ldX = [&](int c) {
#pragma unroll
        for (int u = 0; u < 4; u++) {
            int q = tid + u * 256;
            int m = q >> 3, c4 = q & 7;
            xr[u] = *(const float4*)(X + (size_t)(m0 + m) * DIMD + c * KCH + c4 * 4);
        }
    };
    auto stsA = [&](int s) {
#pragma unroll
        for (int u = 0; u < 4; u++) {
            int q = tid + u * 256;
            int m = q >> 3, c4 = q & 7;
            float v[4] = {xr[u].x, xr[u].y, xr[u].z, xr[u].w};
            __half h[4], l[4];
#pragma unroll
            for (int e = 0; e < 4; e++) {
                h[e] = __float2half_rn(v[e]);
                l[e] = __float2half_rn(v[e] - __half2float(h[e]));
            }
            uint32_t off = m * 64 + ((((c4 >> 1) ^ ((m >> 1) & 3)) << 4)) + ((c4 & 1) << 3);
            *(uint2*)(smem + SM_AHI(s) + off) = make_uint2(pack_h2(h[0], h[1]), pack_h2(h[2], h[3]));
            *(uint2*)(smem + SM_ALO(s) + off) = make_uint2(pack_h2(l[0], l[1]), pack_h2(l[2], l[3]));
        }
    };
    auto cpB = [&](int c, int s) {
        const uint4* base = g_wfrag + ((size_t)nblk * NCHUNK + c) * 1024 + nhalf * 256;
        uint32_t dst = sb + SM_B(s);
#pragma unroll
        for (int u = 0; u < 2; u++) {
            int q = tid + u * 256;   // 0..511 = kk*256 + nt'*32 + lane
            const uint4* src = base + ((q >> 8) << 9) + (q & 255);
            cpasync16(dst + q * 16, src);
        }
    };
    auto compute = [&](int s) {
        const int r15  = lane & 15;
        const int koff = lane >> 4;
        const int xorv = (r15 >> 1) & 3;
#pragma unroll
        for (int kk = 0; kk < 2; kk++) {
            uint32_t ah[2][4], al[2][4];
#pragma unroll
            for (int i = 0; i < 2; i++) {
                int row = wm * 32 + i * 16 + r15;
                uint32_t off = row * 64 + ((((kk * 2 + koff) ^ xorv)) << 4);
                ldsm4(ah[i], sb + SM_AHI(s) + off);
                ldsm4(al[i], sb + SM_ALO(s) + off);
            }
            uint4 bf[4];
#pragma unroll
            for (int j = 0; j < 4; j++) {
                int nt = wn * 4 + j;
                bf[j] = *(const uint4*)(smem + SM_B(s) + ((kk * 256 + nt * 32 + lane) << 4));
            }
#pragma unroll
            for (int i = 0; i < 2; i++) {
#pragma unroll
                for (int j = 0; j < 4; j++) {
                    uint32_t bh[2] = {bf[j].x, bf[j].y};
                    uint32_t bl[2] = {bf[j].z, bf[j].w};
                    float dt[4];
                    mma_f16_z(dt, ah[i], bh);
                    mma_f16(dt, ah[i], bl);
                    mma_f16(dt, al[i], bh);
                    acc[i][j][0] += dt[0];
                    acc[i][j][1] += dt[1];
                    acc[i][j][2] += dt[2];
                    acc[i][j][3] += dt[3];
                }
            }
        }
    };

    ldX(0);
    cpB(0, 0);
    asm volatile("cp.async.commit_group;" ::: "memory");
    stsA(0);
    ldX(1);
    __syncthreads();

    for (int c = 0; c < NCHUNK; c++) {
        const int s = c & 1;
        asm volatile("cp.async.wait_group 0;" ::: "memory");
        __syncthreads();
        if (c + 1 < NCHUNK) {
            cpB(c + 1, s ^ 1);
            asm volatile("cp.async.commit_group;" ::: "memory");
            stsA(s ^ 1);
            if (c + 2 < NCHUNK) ldX(c + 2);
        }
        compute(s);
    }

    const float SCL = 1.f / 4096.f;
#pragma unroll
    for (int i = 0; i < 2; i++) {
        int row0 = m0 + wm * 32 + i * 16 + (lane >> 2);
#pragma unroll
        for (int j = 0; j < 4; j++) {
            int col = n0 + wn * 32 + j * 8 + (lane & 3) * 2;
            *(float2*)(g_logits + (size_t)row0 * NEXP + col) =
                make_float2(acc[i][j][0] * SCL, acc[i][j][1] * SCL);
            *(float2*)(g_logits + (size_t)(row0 + 8) * NEXP + col) =
                make_float2(acc[i][j][2] * SCL, acc[i][j][3] * SCL);
        }
    }
}

// ---------------------------------------------------------------------------
// Shared routing core. DETECT: measure decision margins, flag risky tokens.
// ---------------------------------------------------------------------------
template <bool DETECT>
__device__ __forceinline__ void route_core(float v[8], int lane, int token,
                                           float* __restrict__ wout,
                                           float* __restrict__ iout, int two_out)
{
    float m = v[0];
#pragma unroll
    for (int j = 1; j < 8; j++) m = fmaxf(m, v[j]);
#pragma unroll
    for (int o = 16; o; o >>= 1) m = fmaxf(m, __shfl_xor_sync(0xffffffffu, m, o));

    float e[8], s = 0.f;
#pragma unroll
    for (int j = 0; j < 8; j++) { e[j] = expf(v[j] - m); s += e[j]; }
#pragma unroll
    for (int o = 16; o; o >>= 1) s += __shfl_xor_sync(0xffffffffu, s, o);
    const float inv = 1.f / s;

    float gm[8];
#pragma unroll
    for (int j = 0; j < 8; j++) {
        float g = v[j];
#pragma unroll
        for (int o = 16; o; o >>= 1) g = fmaxf(g, __shfl_xor_sync(0xffffffffu, g, o));
        gm[j] = g;
    }

    unsigned keep = 0;
    float gv4 = 0.f, gv5 = 0.f;
#pragma unroll
    for (int r = 0; r < 5; r++) {
        int best = -1; float bv = -FLT_MAX;
#pragma unroll
        for (int g = 0; g < 8; g++) {
            if (keep & (1u << g)) continue;
            if (gm[g] > bv) { bv = gm[g]; best = g; }
        }
        if (r < 4) keep |= 1u << best;
        if (r == 3) gv4 = bv;
        if (r == 4) gv5 = bv;
    }
    bool risky = DETECT && (gv4 - gv5 < TAU);

    float mv[8];
#pragma unroll
    for (int j = 0; j < 8; j++) mv[j] = ((keep >> j) & 1u) ? e[j] : -FLT_MAX;

    float prev = 0.f;
#pragma unroll
    for (int r = 0; r < 9; r++) {
        float bv = -FLT_MAX; int bi = NEXP;
#pragma unroll
        for (int j = 0; j < 8; j++) {
            int idx = j * 32 + lane;
            if (mv[j] > bv || (mv[j] == bv && idx < bi)) { bv = mv[j]; bi = idx; }
        }
#pragma unroll
        for (int o = 16; o; o >>= 1) {
            float ov = __shfl_xor_sync(0xffffffffu, bv, o);
            int   oi = __shfl_xor_sync(0xffffffffu, bi, o);
            if (ov > bv || (ov == bv && oi < bi)) { bv = ov; bi = oi; }
        }
        if (DETECT && r > 0 && (prev - bv < TAU * prev)) risky = true;
        prev = bv;
        if (r < 8) {
            if (lane == r) {
                wout[(size_t)token * TOPK + r] = bv * inv;
                if (two_out) iout[(size_t)token * TOPK + r] = (float)bi;
            }
            int jj = bi >> 5, ll = bi & 31;
#pragma unroll
            for (int j = 0; j < 8; j++)
                if (j == jj && lane == ll) mv[j] = -FLT_MAX;
        }
    }

    if (DETECT && risky && lane == 0) {
        int pos = atomicAdd(&g_risky_count, 1);
        g_risky[pos] = token;
    }
}

// ---------------------------------------------------------------------------
__global__ void gate_route_kernel(float* __restrict__ wout,
                                  float* __restrict__ iout,
                                  int T, int two_out)
{
    const int warp = (blockIdx.x * blockDim.x + threadIdx.x) >> 5;
    const int lane = threadIdx.x & 31;
    if (warp >= T) return;
    const float* l = g_logits + (size_t)warp * NEXP;
    float v[8];
#pragma unroll
    for (int j = 0; j < 8; j++) v[j] = l[j * 32 + lane];
    route_core<true>(v, lane, warp, wout, iout, two_out);
}

// ---------------------------------------------------------------------------
// Repair v3: one CTA per risky token; thread e streams W row e from the
// k-major transposed copy (coalesced LDG.128, L2-hot) and runs R1's EXACT
// ascending-k fmaf chain. No W staging, no per-chunk syncs.
// ---------------------------------------------------------------------------
__global__ void __launch_bounds__(256)
repair_kernel(const float* __restrict__ X,
              float* __restrict__ wout, float* __restrict__ iout, int two_out)
{
    __shared__ float4 sx[DIMD / 4];   // 16 KB: the token's X row
    __shared__ float  slog[NEXP];

    const int cnt = g_risky_count;
    const int e   = threadIdx.x;

    for (int ti = blockIdx.x; ti < cnt; ti += gridDim.x) {
        const int token = g_risky[ti];

        const float4* xsrc = (const float4*)(X + (size_t)token * DIMD);
#pragma unroll
        for (int u = 0; u < 4; u++)
            sx[e + u * 256] = xsrc[e + u * 256];
        __syncthreads();

        float a = 0.f;
        const float4* wq = g_wq + e;
#pragma unroll 8
        for (int k4 = 0; k4 < DIMD / 4; k4++) {
            float4 w = __ldg(wq + (size_t)k4 * NEXP);
            float4 x = sx[k4];
            a = fmaf(x.x, w.x, a);
            a = fmaf(x.y, w.y, a);
            a = fmaf(x.z, w.z, a);
            a = fmaf(x.w, w.w, a);   // strictly ascending k == R1 chain
        }

        slog[e] = a;
        __syncthreads();
        if (e < 32) {
            float v[8];
#pragma unroll
            for (int j = 0; j < 8; j++) v[j] = slog[j * 32 + e];
            route_core<false>(v, e, token, wout, iout, two_out);
        }
        __syncthreads();
    }
}

// ---------------------------------------------------------------------------
extern "C" void kernel_launch(void* const* d_in, const int* in_sizes, int n_in,
                              void* d_out, int out_size)
{
    const float* X = (const float*)d_in[0];
    const float* W = (const float*)d_in[1];
    const int T = in_sizes[0] / DIMD;   // 16384

    split_w_kernel<<<1024, 256>>>(W);
    transpose_w_kernel<<<1024, 256>>>(W);

    cudaFuncSetAttribute(gate_gemm_f16, cudaFuncAttributeMaxDynamicSharedMemorySize, SM_TOTAL);
    dim3 ggrid(NEXP / 64, T / 128);   // (4, 128) = 512 CTAs, occ 2
    gate_gemm_f16<<<ggrid, 256, SM_TOTAL>>>(X);

    float* wout = (float*)d_out;
    int two_out = (out_size >= 2 * T * TOPK) ? 1 : 0;
    float* iout = wout + (size_t)T * TOPK;
    gate_route_kernel<<<(T * 32 + 255) / 256, 256>>>(wout, iout, T, two_out);

    repair_kernel<<<256, 256>>>(X, wout, iout, two_out);
}